// round 12
// baseline (speedup 1.0000x reference)
#include <cuda_runtime.h>
#include <cuda_bf16.h>

#define LL   512
#define BSZ  32
#define LP1  513
#define ROWF 1539
#define NG   384          // aligned float4 groups per row (same for all shifts)
#define RCA  3.8f

// Scratch: Fa (12 floats, 3x4 row-major) + Fb (12 floats) per (b, l)
__device__ float g_F[BSZ * LL * 24];
// Homogeneous coords table: g_C4[b*513 + m] = (x, y, z, 1)
__device__ __align__(16) float4 g_C4[BSZ * LP1];
__device__ int g_ready[BSZ];   // zero-init; reset each replay by live_kernel
__device__ int g_done[BSZ];    // zero-init; reset each replay by live_kernel

// Affine 3x4 stored as r[0..8] row-major + t[9..11]. C = A @ B.
__device__ __forceinline__ void compose(const float* __restrict__ A,
                                        const float* __restrict__ B,
                                        float* __restrict__ C) {
#pragma unroll
    for (int i = 0; i < 3; i++) {
        const float a0 = A[i * 3 + 0], a1 = A[i * 3 + 1], a2 = A[i * 3 + 2];
        C[i * 3 + 0] = a0 * B[0] + a1 * B[3] + a2 * B[6];
        C[i * 3 + 1] = a0 * B[1] + a1 * B[4] + a2 * B[7];
        C[i * 3 + 2] = a0 * B[2] + a1 * B[5] + a2 * B[8];
        C[9 + i]     = a0 * B[9] + a1 * B[10] + a2 * B[11] + A[9 + i];
    }
}

__device__ __forceinline__ void row_range(int l, int len, int head,
                                          int& g_min, int& g_max) {
    if (l < len) {
        g_min = (3 * l - head + 3) >> 2;
        if (g_min < 0) g_min = 0;
        g_max = (3 * len + 2 - head) >> 2;
        if (g_max > NG - 1) g_max = NG - 1;
    } else {
        g_min = NG;        // dead row: outside-set = all groups
        g_max = NG - 1;
    }
}

// ---------------- zero_kernel: all structurally-zero groups -----------------
// Depends only on lens. Fires PDL trigger immediately so scan/live can launch.
__global__ __launch_bounds__(256) void zero_kernel(const int* __restrict__ lens,
                                                   float* __restrict__ out) {
#if __CUDA_ARCH__ >= 900
    cudaTriggerProgrammaticLaunchCompletion();
#endif
    const int l   = blockIdx.x;
    const int b   = blockIdx.y;
    const int tid = threadIdx.x;
    const int len = __ldg(&lens[b]);
    const int head = (4 - ((3 * l) & 3)) & 3;

    int g_min, g_max;
    row_range(l, len, head, g_min, g_max);
    const int dead1   = g_min;               // groups [0, g_min)
    const int dead2   = NG - 1 - g_max;      // groups (g_max, NG)
    const int deadTot = dead1 + dead2;

    const size_t base0 = ((size_t)(b * 2 + 0) * LL + l) * ROWF;
    const size_t base1 = base0 + (size_t)LL * ROWF;
    const float4 z4 = make_float4(0.f, 0.f, 0.f, 0.f);

    for (int t = tid; t < 2 * deadTot; t += 256) {
        const int s   = (t >= deadTot);
        const int idx = t - (s ? deadTot : 0);
        const int g   = (idx < dead1) ? idx : (g_max + 1 + (idx - dead1));
        __stcs((float4*)(out + (s ? base1 : base0) + head + 4 * g), z4);
    }
    // Dead rows: also write the 3+3 boundary scalars (live_kernel skips them).
    if (l >= len && tid < 6) {
        const int s  = tid >= 3;
        const int jj = tid - (s ? 3 : 0);
        const int e  = (jj < head) ? jj : (head + 4 * NG + (jj - head));
        out[(s ? base1 : base0) + e] = 0.f;
    }
}

// ---------------- scan_kernel: prefix product + F build --------------------
__global__ __launch_bounds__(LL) void scan_kernel(const float* __restrict__ angles,
                                                  const float* __restrict__ coords) {
#if __CUDA_ARCH__ >= 900
    cudaTriggerProgrammaticLaunchCompletion();   // release live launch; handshake guards g_F
#endif
    __shared__ float wTot[16][13];
    const int b    = blockIdx.x;
    const int l    = threadIdx.x;
    const int w    = l >> 5;
    const int lane = l & 31;

    {
        const float* c = coords + (size_t)b * ROWF + 3 * l;
        g_C4[b * LP1 + l] = make_float4(c[0], c[1], c[2], 1.f);
        if (l == 0) {
            const float* c2 = coords + (size_t)b * ROWF + 3 * 512;
            g_C4[b * LP1 + 512] = make_float4(c2[0], c2[1], c2[2], 1.f);
        }
    }

    const float alpha = angles[(b * 2 + 0) * LL + l];
    const float beta  = angles[(b * 2 + 1) * LL + l];
    float sa, ca, sb, cb;
    sincosf(alpha, &sa, &ca);
    sincosf(beta,  &sb, &cb);

    float M[12];
    M[0] = ca;  M[1] = -sa * cb; M[2] = sa * sb;
    M[3] = sa;  M[4] = ca * cb;  M[5] = -ca * sb;
    M[6] = 0.f; M[7] = sb;       M[8] = cb;
    M[9] = RCA * ca; M[10] = RCA * sa; M[11] = 0.f;

#pragma unroll
    for (int off = 1; off < 32; off <<= 1) {
        float Lf[12];
#pragma unroll
        for (int k = 0; k < 12; k++) Lf[k] = __shfl_up_sync(0xffffffffu, M[k], off);
        if (lane >= off) {
            float T[12];
            compose(Lf, M, T);
#pragma unroll
            for (int k = 0; k < 12; k++) M[k] = T[k];
        }
    }
    if (lane == 31) {
#pragma unroll
        for (int k = 0; k < 12; k++) wTot[w][k] = M[k];
    }
    __syncthreads();

    if (w == 0) {
        float S[12];
        if (lane < 16) {
#pragma unroll
            for (int k = 0; k < 12; k++) S[k] = wTot[lane][k];
        } else {
            S[0] = 1.f; S[1] = 0.f; S[2] = 0.f;
            S[3] = 0.f; S[4] = 1.f; S[5] = 0.f;
            S[6] = 0.f; S[7] = 0.f; S[8] = 1.f;
            S[9] = 0.f; S[10] = 0.f; S[11] = 0.f;
        }
#pragma unroll
        for (int off = 1; off < 16; off <<= 1) {
            float Lf[12];
#pragma unroll
            for (int k = 0; k < 12; k++) Lf[k] = __shfl_up_sync(0xffffffffu, S[k], off);
            if (lane >= off && lane < 16) {
                float T[12];
                compose(Lf, S, T);
#pragma unroll
                for (int k = 0; k < 12; k++) S[k] = T[k];
            }
        }
        if (lane < 16) {
#pragma unroll
            for (int k = 0; k < 12; k++) wTot[lane][k] = S[k];
        }
    }
    __syncthreads();

    float Fin[12];
    if (w > 0) {
        float P[12];
#pragma unroll
        for (int k = 0; k < 12; k++) P[k] = wTot[w - 1][k];
        compose(P, M, Fin);
    } else {
#pragma unroll
        for (int k = 0; k < 12; k++) Fin[k] = M[k];
    }

    float Mp[12];
#pragma unroll
    for (int k = 0; k < 9; k++) Mp[k] = __shfl_up_sync(0xffffffffu, Fin[k], 1);
    if (lane == 0) {
        if (w == 0) {
            Mp[0] = 1.f; Mp[1] = 0.f; Mp[2] = 0.f;
            Mp[3] = 0.f; Mp[4] = 1.f; Mp[5] = 0.f;
            Mp[6] = 0.f; Mp[7] = 0.f; Mp[8] = 1.f;
        } else {
#pragma unroll
            for (int k = 0; k < 9; k++) Mp[k] = wTot[w - 1][k];
        }
    }
    Mp[9] = 0.f; Mp[10] = 0.f; Mp[11] = 0.f;

    float Mi[12];
    Mi[0] = Fin[0]; Mi[1] = Fin[3]; Mi[2] = Fin[6];
    Mi[3] = Fin[1]; Mi[4] = Fin[4]; Mi[5] = Fin[7];
    Mi[6] = Fin[2]; Mi[7] = Fin[5]; Mi[8] = Fin[8];
    Mi[9]  = -(Mi[0] * Fin[9] + Mi[1] * Fin[10] + Mi[2] * Fin[11]);
    Mi[10] = -(Mi[3] * Fin[9] + Mi[4] * Fin[10] + Mi[5] * Fin[11]);
    Mi[11] = -(Mi[6] * Fin[9] + Mi[7] * Fin[10] + Mi[8] * Fin[11]);

    float Da[12];
    Da[0] = -sa; Da[1] = -ca * cb; Da[2] = ca * sb;
    Da[3] = ca;  Da[4] = -sa * cb; Da[5] = sa * sb;
    Da[6] = 0.f; Da[7] = 0.f;      Da[8] = 0.f;
    Da[9] = -RCA * sa; Da[10] = RCA * ca; Da[11] = 0.f;

    float Db[12];
    Db[0] = 0.f; Db[1] = sa * sb;  Db[2] = sa * cb;
    Db[3] = 0.f; Db[4] = -ca * sb; Db[5] = -ca * cb;
    Db[6] = 0.f; Db[7] = cb;       Db[8] = -sb;
    Db[9] = 0.f; Db[10] = 0.f;     Db[11] = 0.f;

    float G[12], Fa[12], Fb[12];
    compose(Da, Mi, G);
    compose(Mp, G, Fa);
    compose(Db, Mi, G);
    compose(Mp, G, Fb);

    float* o = &g_F[(b * LL + l) * 24];
#pragma unroll
    for (int i = 0; i < 3; i++) {
        o[i * 4 + 0] = Fa[i * 3 + 0];
        o[i * 4 + 1] = Fa[i * 3 + 1];
        o[i * 4 + 2] = Fa[i * 3 + 2];
        o[i * 4 + 3] = Fa[9 + i];
        o[12 + i * 4 + 0] = Fb[i * 3 + 0];
        o[12 + i * 4 + 1] = Fb[i * 3 + 1];
        o[12 + i * 4 + 2] = Fb[i * 3 + 2];
        o[12 + i * 4 + 3] = Fb[9 + i];
    }

    __threadfence();
    __syncthreads();
    if (threadIdx.x == 0) atomicExch(&g_ready[b], 1);
}

// ---------------- live_kernel: live groups + boundary scalars ---------------
__global__ __launch_bounds__(256) void live_kernel(const int* __restrict__ lens,
                                                   float* __restrict__ out) {
    const int l   = blockIdx.x;
    const int b   = blockIdx.y;
    const int tid = threadIdx.x;
    const int len = __ldg(&lens[b]);
    const bool alive = (l < len);

    if (alive) {
        // Wait for this batch's scan results.
        if (tid == 0) {
            while (atomicAdd(&g_ready[b], 0) == 0) __nanosleep(64);
        }
        __syncthreads();
        __threadfence();

        const int head = (4 - ((3 * l) & 3)) & 3;
        int g_min, g_max;
        row_range(l, len, head, g_min, g_max);
        const int nLive = g_max - g_min + 1;

        const size_t base0 = ((size_t)(b * 2 + 0) * LL + l) * ROWF;
        const size_t base1 = base0 + (size_t)LL * ROWF;
        const float4* C4 = g_C4 + b * LP1;
        const float4* Fp = (const float4*)&g_F[(b * LL + l) * 24];

        for (int t = tid; t < 2 * nLive; t += 256) {
            const int s = (t >= nLive);
            const int g = g_min + (t - (s ? nLive : 0));
            const int e0 = head + 4 * g;
            const int m0 = e0 / 3;
            const int c0 = e0 - 3 * m0;

            const float4 F0 = __ldg(&Fp[s * 3 + 0]);
            const float4 F1 = __ldg(&Fp[s * 3 + 1]);
            const float4 F2 = __ldg(&Fp[s * 3 + 2]);
            const float4 q0 = __ldg(&C4[m0]);
            const float4 q1 = __ldg(&C4[m0 + 1]);
            const bool on0 = (m0 > l) && (m0 <= len);
            const bool on1 = (m0 + 1 > l) && (m0 + 1 <= len);

            const float d00 = on0 ? (F0.x * q0.x + F0.y * q0.y + F0.z * q0.z + F0.w) : 0.f;
            const float d01 = on0 ? (F1.x * q0.x + F1.y * q0.y + F1.z * q0.z + F1.w) : 0.f;
            const float d02 = on0 ? (F2.x * q0.x + F2.y * q0.y + F2.z * q0.z + F2.w) : 0.f;
            const float d10 = on1 ? (F0.x * q1.x + F0.y * q1.y + F0.z * q1.z + F0.w) : 0.f;
            const float d11 = on1 ? (F1.x * q1.x + F1.y * q1.y + F1.z * q1.z + F1.w) : 0.f;
            const float d12 = on1 ? (F2.x * q1.x + F2.y * q1.y + F2.z * q1.z + F2.w) : 0.f;

            float4 o4;
            o4.x = (c0 == 0) ? d00 : (c0 == 1) ? d01 : d02;
            o4.y = (c0 == 0) ? d01 : (c0 == 1) ? d02 : d10;
            o4.z = (c0 == 0) ? d02 : (c0 == 1) ? d10 : d11;
            o4.w = (c0 == 0) ? d10 : (c0 == 1) ? d11 : d12;
            __stcs((float4*)(out + (s ? base1 : base0) + e0), o4);
        }

        // 3+3 boundary scalars for alive rows (masked values).
        if (tid < 6) {
            const int s  = tid >= 3;
            const int jj = tid - (s ? 3 : 0);
            const int e  = (jj < head) ? jj : (head + 4 * NG + (jj - head));
            const int m  = e / 3;
            const int c  = e - 3 * m;
            const bool on = (m > l) && (m <= len);
            float val = 0.f;
            if (on) {
                const float4 Fc = __ldg(&Fp[s * 3 + c]);
                const float4 q  = __ldg(&C4[m]);
                val = Fc.x * q.x + Fc.y * q.y + Fc.z * q.z + Fc.w;
            }
            out[(s ? base1 : base0) + e] = val;
        }
        __syncthreads();
    }

    // Every live block (alive or not) checks in; last one resets the handshake.
    if (tid == 0) {
        const int d = atomicAdd(&g_done[b], 1);
        if (d == LL - 1) {
            g_done[b]  = 0;
            g_ready[b] = 0;
        }
    }
}

extern "C" void kernel_launch(void* const* d_in, const int* in_sizes, int n_in,
                              void* d_out, int out_size) {
    const float* angles = (const float*)d_in[0];   // (32, 2, 512)
    const float* coords = (const float*)d_in[1];   // (32, 1539)
    const int*   lens   = (const int*)d_in[2];     // (32,)
    float* out = (float*)d_out;

    cudaLaunchAttribute pss[1];
    pss[0].id = cudaLaunchAttributeProgrammaticStreamSerialization;
    pss[0].val.programmaticStreamSerializationAllowed = 1;

    // 1) zero-fill (independent of scan; triggers PDL at start)
    zero_kernel<<<dim3(LL, BSZ), 256>>>(lens, out);

    // 2) scan (PSS: launches as soon as zero triggers; triggers at its start)
    {
        cudaLaunchConfig_t cfg = {};
        cfg.gridDim = dim3(BSZ); cfg.blockDim = dim3(LL);
        cfg.attrs = pss; cfg.numAttrs = 1; cfg.stream = 0;
        cudaLaunchKernelEx(&cfg, scan_kernel, angles, coords);
    }

    // 3) live writer (PSS: launches as soon as scan triggers; flag handshake
    //    guards g_F/g_C4 reads; addresses disjoint from zero_kernel)
    {
        cudaLaunchConfig_t cfg = {};
        cfg.gridDim = dim3(LL, BSZ); cfg.blockDim = dim3(256);
        cfg.attrs = pss; cfg.numAttrs = 1; cfg.stream = 0;
        cudaLaunchKernelEx(&cfg, live_kernel, lens, out);
    }
}

// round 17
// speedup vs baseline: 1.4218x; 1.4218x over previous
#include <cuda_runtime.h>
#include <cuda_bf16.h>

#define LL   512
#define BSZ  32
#define LP1  513
#define ROWF 1539
#define NG   384          // aligned float4 groups per row (same for all shifts)
#define RCA  3.8f

// Scratch: Fa (12 floats, 3x4 row-major) + Fb (12 floats) per (b, l)
__device__ float g_F[BSZ * LL * 24];
// Homogeneous coords table: g_C4[b*513 + m] = (x, y, z, 1)
__device__ __align__(16) float4 g_C4[BSZ * LP1];

// Affine 3x4 stored as r[0..8] row-major + t[9..11]. C = A @ B.
__device__ __forceinline__ void compose(const float* __restrict__ A,
                                        const float* __restrict__ B,
                                        float* __restrict__ C) {
#pragma unroll
    for (int i = 0; i < 3; i++) {
        const float a0 = A[i * 3 + 0], a1 = A[i * 3 + 1], a2 = A[i * 3 + 2];
        C[i * 3 + 0] = a0 * B[0] + a1 * B[3] + a2 * B[6];
        C[i * 3 + 1] = a0 * B[1] + a1 * B[4] + a2 * B[7];
        C[i * 3 + 2] = a0 * B[2] + a1 * B[5] + a2 * B[8];
        C[9 + i]     = a0 * B[9] + a1 * B[10] + a2 * B[11] + A[9 + i];
    }
}

__device__ __forceinline__ void row_range(int l, int len, int head,
                                          int& g_min, int& g_max) {
    if (l < len) {
        g_min = (3 * l - head + 3) >> 2;
        if (g_min < 0) g_min = 0;
        g_max = (3 * len + 2 - head) >> 2;
        if (g_max > NG - 1) g_max = NG - 1;
    } else {
        g_min = NG;        // dead row: all groups are zero
        g_max = NG - 1;
    }
}

// ---------------- scan_kernel: prefix product + F build --------------------
__global__ __launch_bounds__(LL) void scan_kernel(const float* __restrict__ angles,
                                                  const float* __restrict__ coords) {
    __shared__ float wTot[16][13];
    const int b    = blockIdx.x;
    const int l    = threadIdx.x;
    const int w    = l >> 5;
    const int lane = l & 31;

    {
        const float* c = coords + (size_t)b * ROWF + 3 * l;
        g_C4[b * LP1 + l] = make_float4(c[0], c[1], c[2], 1.f);
        if (l == 0) {
            const float* c2 = coords + (size_t)b * ROWF + 3 * 512;
            g_C4[b * LP1 + 512] = make_float4(c2[0], c2[1], c2[2], 1.f);
        }
    }

    const float alpha = angles[(b * 2 + 0) * LL + l];
    const float beta  = angles[(b * 2 + 1) * LL + l];
    float sa, ca, sb, cb;
    sincosf(alpha, &sa, &ca);
    sincosf(beta,  &sb, &cb);

    float M[12];
    M[0] = ca;  M[1] = -sa * cb; M[2] = sa * sb;
    M[3] = sa;  M[4] = ca * cb;  M[5] = -ca * sb;
    M[6] = 0.f; M[7] = sb;       M[8] = cb;
    M[9] = RCA * ca; M[10] = RCA * sa; M[11] = 0.f;

#pragma unroll
    for (int off = 1; off < 32; off <<= 1) {
        float Lf[12];
#pragma unroll
        for (int k = 0; k < 12; k++) Lf[k] = __shfl_up_sync(0xffffffffu, M[k], off);
        if (lane >= off) {
            float T[12];
            compose(Lf, M, T);
#pragma unroll
            for (int k = 0; k < 12; k++) M[k] = T[k];
        }
    }
    if (lane == 31) {
#pragma unroll
        for (int k = 0; k < 12; k++) wTot[w][k] = M[k];
    }
    __syncthreads();

    if (w == 0) {
        float S[12];
        if (lane < 16) {
#pragma unroll
            for (int k = 0; k < 12; k++) S[k] = wTot[lane][k];
        } else {
            S[0] = 1.f; S[1] = 0.f; S[2] = 0.f;
            S[3] = 0.f; S[4] = 1.f; S[5] = 0.f;
            S[6] = 0.f; S[7] = 0.f; S[8] = 1.f;
            S[9] = 0.f; S[10] = 0.f; S[11] = 0.f;
        }
#pragma unroll
        for (int off = 1; off < 16; off <<= 1) {
            float Lf[12];
#pragma unroll
            for (int k = 0; k < 12; k++) Lf[k] = __shfl_up_sync(0xffffffffu, S[k], off);
            if (lane >= off && lane < 16) {
                float T[12];
                compose(Lf, S, T);
#pragma unroll
                for (int k = 0; k < 12; k++) S[k] = T[k];
            }
        }
        if (lane < 16) {
#pragma unroll
            for (int k = 0; k < 12; k++) wTot[lane][k] = S[k];
        }
    }
    __syncthreads();

    float Fin[12];
    if (w > 0) {
        float P[12];
#pragma unroll
        for (int k = 0; k < 12; k++) P[k] = wTot[w - 1][k];
        compose(P, M, Fin);
    } else {
#pragma unroll
        for (int k = 0; k < 12; k++) Fin[k] = M[k];
    }

    float Mp[12];
#pragma unroll
    for (int k = 0; k < 9; k++) Mp[k] = __shfl_up_sync(0xffffffffu, Fin[k], 1);
    if (lane == 0) {
        if (w == 0) {
            Mp[0] = 1.f; Mp[1] = 0.f; Mp[2] = 0.f;
            Mp[3] = 0.f; Mp[4] = 1.f; Mp[5] = 0.f;
            Mp[6] = 0.f; Mp[7] = 0.f; Mp[8] = 1.f;
        } else {
#pragma unroll
            for (int k = 0; k < 9; k++) Mp[k] = wTot[w - 1][k];
        }
    }
    Mp[9] = 0.f; Mp[10] = 0.f; Mp[11] = 0.f;

    float Mi[12];
    Mi[0] = Fin[0]; Mi[1] = Fin[3]; Mi[2] = Fin[6];
    Mi[3] = Fin[1]; Mi[4] = Fin[4]; Mi[5] = Fin[7];
    Mi[6] = Fin[2]; Mi[7] = Fin[5]; Mi[8] = Fin[8];
    Mi[9]  = -(Mi[0] * Fin[9] + Mi[1] * Fin[10] + Mi[2] * Fin[11]);
    Mi[10] = -(Mi[3] * Fin[9] + Mi[4] * Fin[10] + Mi[5] * Fin[11]);
    Mi[11] = -(Mi[6] * Fin[9] + Mi[7] * Fin[10] + Mi[8] * Fin[11]);

    float Da[12];
    Da[0] = -sa; Da[1] = -ca * cb; Da[2] = ca * sb;
    Da[3] = ca;  Da[4] = -sa * cb; Da[5] = sa * sb;
    Da[6] = 0.f; Da[7] = 0.f;      Da[8] = 0.f;
    Da[9] = -RCA * sa; Da[10] = RCA * ca; Da[11] = 0.f;

    float Db[12];
    Db[0] = 0.f; Db[1] = sa * sb;  Db[2] = sa * cb;
    Db[3] = 0.f; Db[4] = -ca * sb; Db[5] = -ca * cb;
    Db[6] = 0.f; Db[7] = cb;       Db[8] = -sb;
    Db[9] = 0.f; Db[10] = 0.f;     Db[11] = 0.f;

    float G[12], Fa[12], Fb[12];
    compose(Da, Mi, G);
    compose(Mp, G, Fa);
    compose(Db, Mi, G);
    compose(Mp, G, Fb);

    float* o = &g_F[(b * LL + l) * 24];
#pragma unroll
    for (int i = 0; i < 3; i++) {
        o[i * 4 + 0] = Fa[i * 3 + 0];
        o[i * 4 + 1] = Fa[i * 3 + 1];
        o[i * 4 + 2] = Fa[i * 3 + 2];
        o[i * 4 + 3] = Fa[9 + i];
        o[12 + i * 4 + 0] = Fb[i * 3 + 0];
        o[12 + i * 4 + 1] = Fb[i * 3 + 1];
        o[12 + i * 4 + 2] = Fb[i * 3 + 2];
        o[12 + i * 4 + 3] = Fb[9 + i];
    }

    __threadfence();
#if __CUDA_ARCH__ >= 900
    cudaTriggerProgrammaticLaunchCompletion();
#endif
}

// Two-phase emit: phase 1 (scan-independent) streams all structurally-zero
// groups; mid-kernel PDL sync; phase 2 writes live groups. 384 threads,
// thread == group index; l interleaved stride-128 for balance.
__global__ __launch_bounds__(384) void emit_kernel(const int* __restrict__ lens,
                                                   float* __restrict__ out) {
    const int b   = blockIdx.y;
    const int g   = threadIdx.x;           // 0..383 == group index
    const int len = __ldg(&lens[b]);
    const float4 z4 = make_float4(0.f, 0.f, 0.f, 0.f);

    // ---- Phase 1: zero groups + dead-row boundary scalars (no scan dep) ----
#pragma unroll
    for (int dl = 0; dl < 4; dl++) {
        const int l = blockIdx.x + (dl << 7);
        const int head = (4 - ((3 * l) & 3)) & 3;
        int g_min, g_max;
        row_range(l, len, head, g_min, g_max);

        const size_t base0 = ((size_t)(b * 2 + 0) * LL + l) * ROWF;
        const size_t base1 = base0 + (size_t)LL * ROWF;

        if (g < g_min || g > g_max) {
            __stcs((float4*)(out + base0 + head + 4 * g), z4);
            __stcs((float4*)(out + base1 + head + 4 * g), z4);
        }
        if (l >= len && g < 6) {
            const int s  = g >= 3;
            const int jj = g - (s ? 3 : 0);
            const int e  = (jj < head) ? jj : (head + 4 * NG + (jj - head));
            out[(s ? base1 : base0) + e] = 0.f;
        }
    }

#if __CUDA_ARCH__ >= 900
    cudaGridDependencySynchronize();   // wait for scan's g_F / g_C4
#else
    __threadfence();
#endif
    const float4* C4 = g_C4 + b * LP1;

    // ---- Phase 2: live groups + alive-row boundary scalars ----
#pragma unroll 1
    for (int dl = 0; dl < 4; dl++) {
        const int l = blockIdx.x + (dl << 7);
        if (l >= len) continue;
        const int head = (4 - ((3 * l) & 3)) & 3;
        int g_min, g_max;
        row_range(l, len, head, g_min, g_max);

        const size_t base0 = ((size_t)(b * 2 + 0) * LL + l) * ROWF;
        const size_t base1 = base0 + (size_t)LL * ROWF;
        const float4* Fp = (const float4*)&g_F[(b * LL + l) * 24];

        if (g >= g_min && g <= g_max) {
            const float4 A0 = __ldg(&Fp[0]);
            const float4 A1 = __ldg(&Fp[1]);
            const float4 A2 = __ldg(&Fp[2]);
            const float4 B0 = __ldg(&Fp[3]);
            const float4 B1 = __ldg(&Fp[4]);
            const float4 B2 = __ldg(&Fp[5]);

            const int e0 = head + 4 * g;
            const int m0 = e0 / 3;
            const int c0 = e0 - 3 * m0;
            const float4 q0 = __ldg(&C4[m0]);
            const float4 q1 = __ldg(&C4[m0 + 1]);
            const bool on0 = (m0 > l) && (m0 <= len);
            const bool on1 = (m0 + 1 > l) && (m0 + 1 <= len);

            const float a00 = on0 ? (A0.x * q0.x + A0.y * q0.y + A0.z * q0.z + A0.w) : 0.f;
            const float a01 = on0 ? (A1.x * q0.x + A1.y * q0.y + A1.z * q0.z + A1.w) : 0.f;
            const float a02 = on0 ? (A2.x * q0.x + A2.y * q0.y + A2.z * q0.z + A2.w) : 0.f;
            const float a10 = on1 ? (A0.x * q1.x + A0.y * q1.y + A0.z * q1.z + A0.w) : 0.f;
            const float a11 = on1 ? (A1.x * q1.x + A1.y * q1.y + A1.z * q1.z + A1.w) : 0.f;
            const float a12 = on1 ? (A2.x * q1.x + A2.y * q1.y + A2.z * q1.z + A2.w) : 0.f;

            const float b00 = on0 ? (B0.x * q0.x + B0.y * q0.y + B0.z * q0.z + B0.w) : 0.f;
            const float b01 = on0 ? (B1.x * q0.x + B1.y * q0.y + B1.z * q0.z + B1.w) : 0.f;
            const float b02 = on0 ? (B2.x * q0.x + B2.y * q0.y + B2.z * q0.z + B2.w) : 0.f;
            const float b10 = on1 ? (B0.x * q1.x + B0.y * q1.y + B0.z * q1.z + B0.w) : 0.f;
            const float b11 = on1 ? (B1.x * q1.x + B1.y * q1.y + B1.z * q1.z + B1.w) : 0.f;
            const float b12 = on1 ? (B2.x * q1.x + B2.y * q1.y + B2.z * q1.z + B2.w) : 0.f;

            float4 oa, ob;
            oa.x = (c0 == 0) ? a00 : (c0 == 1) ? a01 : a02;
            oa.y = (c0 == 0) ? a01 : (c0 == 1) ? a02 : a10;
            oa.z = (c0 == 0) ? a02 : (c0 == 1) ? a10 : a11;
            oa.w = (c0 == 0) ? a10 : (c0 == 1) ? a11 : a12;
            ob.x = (c0 == 0) ? b00 : (c0 == 1) ? b01 : b02;
            ob.y = (c0 == 0) ? b01 : (c0 == 1) ? b02 : b10;
            ob.z = (c0 == 0) ? b02 : (c0 == 1) ? b10 : b11;
            ob.w = (c0 == 0) ? b10 : (c0 == 1) ? b11 : b12;

            __stcs((float4*)(out + base0 + e0), oa);
            __stcs((float4*)(out + base1 + e0), ob);
        }

        if (g < 6) {
            const int s  = g >= 3;
            const int jj = g - (s ? 3 : 0);
            const int e  = (jj < head) ? jj : (head + 4 * NG + (jj - head));
            const int m  = e / 3;
            const int c  = e - 3 * m;
            const bool on = (m > l) && (m <= len);
            float val = 0.f;
            if (on) {
                const float4 Fc = __ldg(&Fp[s * 3 + c]);
                const float4 q  = __ldg(&C4[m]);
                val = Fc.x * q.x + Fc.y * q.y + Fc.z * q.z + Fc.w;
            }
            out[(s ? base1 : base0) + e] = val;
        }
    }
}

extern "C" void kernel_launch(void* const* d_in, const int* in_sizes, int n_in,
                              void* d_out, int out_size) {
    const float* angles = (const float*)d_in[0];   // (32, 2, 512)
    const float* coords = (const float*)d_in[1];   // (32, 1539)
    const int*   lens   = (const int*)d_in[2];     // (32,)
    float* out = (float*)d_out;

    scan_kernel<<<BSZ, LL>>>(angles, coords);

    // Emit launches immediately after scan *triggers*; phase 1 (zero stream)
    // overlaps scan execution, phase 2 gated by cudaGridDependencySynchronize.
    cudaLaunchConfig_t cfg = {};
    cfg.gridDim  = dim3(128, BSZ);
    cfg.blockDim = dim3(384);
    cfg.dynamicSmemBytes = 0;
    cfg.stream = 0;
    cudaLaunchAttribute attr[1];
    attr[0].id = cudaLaunchAttributeProgrammaticStreamSerialization;
    attr[0].val.programmaticStreamSerializationAllowed = 1;
    cfg.attrs = attr;
    cfg.numAttrs = 1;
    cudaLaunchKernelEx(&cfg, emit_kernel, lens, out);
}